// round 1
// baseline (speedup 1.0000x reference)
#include <cuda_runtime.h>
#include <cstdint>

// ---------------- problem constants ----------------
#define BATCH   16
#define CIN     3
#define HIN     256
#define WIN     256
#define DMODEL  256
#define KCODES  512
#define HP      128          // pooled H
#define WP      128          // pooled W
#define NROWS   (BATCH*HP*WP)            // 262144
#define QUANT_ELEMS ((long long)BATCH*DMODEL*HP*WP)  // 67108864
#define IDX_ELEMS   (BATCH*HP*WP)        // 262144
#define BN_EPS 1e-5f

// ---------------- scratch (static device memory; no allocations) ----------------
__device__ float               g_fmap[(long long)NROWS * DMODEL];   // [row][d]
__device__ unsigned long long  g_best[NROWS];
__device__ float               g_c2[KCODES];
__device__ float               g_conv_partial[2048];
__device__ float               g_vq_partial[2048];

// ---------------- f32x2 helpers (FFMA2 path, sm_103a) ----------------
__device__ __forceinline__ unsigned long long pack2(float a, float b) {
    unsigned long long r;
    asm("mov.b64 %0, {%1, %2};" : "=l"(r) : "f"(a), "f"(b));
    return r;
}
__device__ __forceinline__ void unpack2(unsigned long long v, float& a, float& b) {
    asm("mov.b64 {%0, %1}, %2;" : "=f"(a), "=f"(b) : "l"(v));
}
__device__ __forceinline__ void fma2(unsigned long long& acc,
                                     unsigned long long a, unsigned long long b) {
    asm("fma.rn.f32x2 %0, %1, %2, %3;" : "=l"(acc) : "l"(a), "l"(b), "l"(acc));
}

// ordered-float encoding: monotonic uint mapping for atomicMin on distances
__device__ __forceinline__ unsigned fenc(float f) {
    unsigned u = __float_as_uint(f);
    return (u & 0x80000000u) ? ~u : (u | 0x80000000u);
}
__device__ __forceinline__ float fdec(unsigned e) {
    unsigned u = (e & 0x80000000u) ? (e ^ 0x80000000u) : ~e;
    return __uint_as_float(u);
}

// =====================================================================
// Kernel 1: fused conv3x3(3->256) + bias + maxpool2x2 + BN + exact GELU
// grid: 2048 = (b, ph);  block: 256 threads = one output channel each
// also produces per-block sum of fmap^2 (for commit loss)
// =====================================================================
__global__ __launch_bounds__(256) void conv_kernel(
    const float* __restrict__ x, const float* __restrict__ cw,
    const float* __restrict__ cbias,
    const float* __restrict__ gam, const float* __restrict__ bet,
    const float* __restrict__ mu,  const float* __restrict__ var)
{
    const int bx = blockIdx.x;
    const int b  = bx >> 7;
    const int ph = bx & 127;
    const int d  = threadIdx.x;

    __shared__ __align__(16) float sIn[3][4][258];   // rows 2ph-1..2ph+2, cols -1..256
    __shared__ float red[256];

    const int h0 = 2 * ph - 1;
    for (int t = threadIdx.x; t < 3 * 4 * 258; t += 256) {
        int c   = t / 1032;
        int rem = t - c * 1032;
        int i   = rem / 258;
        int j   = rem - i * 258;
        int gr  = h0 + i;
        int gc  = j - 1;
        float v = 0.f;
        if ((unsigned)gr < 256u && (unsigned)gc < 256u)
            v = x[(((b * 3 + c) << 8) + gr) * 256 + gc];
        sIn[c][i][j] = v;
    }

    // per-channel weights packed {w,w} for FFMA2
    unsigned long long w2[27];
#pragma unroll
    for (int j = 0; j < 27; j++) {
        float wv = cw[d * 27 + j];
        w2[j] = pack2(wv, wv);
    }
    const float bias = cbias[d];
    const float inv  = gam[d] * rsqrtf(var[d] + BN_EPS);
    const float shf  = bet[d] - mu[d] * inv;

    __syncthreads();

    float sumsq = 0.f;
    const long long rowOut = (long long)bx * 128;

    for (int pw = 0; pw < 128; ++pw) {
        unsigned long long acc0 = 0ull, acc1 = 0ull;  // {s0,s1} for r=0, r=1
#pragma unroll
        for (int c = 0; c < 3; c++) {
            const int wb = c * 9;
#pragma unroll
            for (int ro = 0; ro < 4; ro++) {
                const float* p = &sIn[c][ro][2 * pw];
                unsigned long long g01 = *reinterpret_cast<const unsigned long long*>(p);
                unsigned long long g23 = *reinterpret_cast<const unsigned long long*>(p + 2);
                float f0, f1, f2, f3;
                unpack2(g01, f0, f1);
                unpack2(g23, f2, f3);
                unsigned long long g12 = pack2(f1, f2);
                // output r uses kh = ro - r (valid for 0<=kh<=2)
                if (ro <= 2) { // r = 0, kh = ro
                    fma2(acc0, g01, w2[wb + ro * 3 + 0]);
                    fma2(acc0, g12, w2[wb + ro * 3 + 1]);
                    fma2(acc0, g23, w2[wb + ro * 3 + 2]);
                }
                if (ro >= 1) { // r = 1, kh = ro-1
                    fma2(acc1, g01, w2[wb + (ro - 1) * 3 + 0]);
                    fma2(acc1, g12, w2[wb + (ro - 1) * 3 + 1]);
                    fma2(acc1, g23, w2[wb + (ro - 1) * 3 + 2]);
                }
            }
        }
        float a0, a1, b0, b1;
        unpack2(acc0, a0, a1);
        unpack2(acc1, b0, b1);
        float m = fmaxf(fmaxf(a0, a1), fmaxf(b0, b1)) + bias;
        float v = m * inv + shf;
        float g = 0.5f * v * (1.0f + erff(v * 0.7071067811865476f));
        g_fmap[(rowOut + pw) * DMODEL + d] = g;
        sumsq += g * g;
    }

    // block reduction of sum of squares
    red[threadIdx.x] = sumsq;
    __syncthreads();
    for (int s = 128; s > 0; s >>= 1) {
        if (threadIdx.x < s) red[threadIdx.x] += red[threadIdx.x + s];
        __syncthreads();
    }
    if (threadIdx.x == 0) g_conv_partial[bx] = red[0];
}

// =====================================================================
// Kernel 2: codebook squared norms
// =====================================================================
__global__ void c2_kernel(const float* __restrict__ cbk)
{
    int warp = (blockIdx.x * blockDim.x + threadIdx.x) >> 5;
    int lane = threadIdx.x & 31;
    int nwarp = (gridDim.x * blockDim.x) >> 5;
    for (int k = warp; k < KCODES; k += nwarp) {
        float s = 0.f;
        for (int t = lane; t < DMODEL; t += 32) {
            float v = cbk[k * DMODEL + t];
            s += v * v;
        }
#pragma unroll
        for (int off = 16; off >= 1; off >>= 1)
            s += __shfl_xor_sync(0xffffffffu, s, off);
        if (lane == 0) g_c2[k] = s;
    }
}

// =====================================================================
// Kernel 3: VQ distance GEMM + argmin  (fp32 via packed FFMA2)
// grid: (4 code-blocks, 2048 row-blocks); block 256 threads
// tile: 128 rows x 128 codes, TK=16; thread: 8 rows x 8 codes (4 pairs)
// =====================================================================
#define TKV 16
__global__ __launch_bounds__(256) void vq_kernel(const float* __restrict__ cbk)
{
    __shared__ __align__(16) float2 As2[TKV][130];  // [kk][row] duplicated {a,a}
    __shared__ __align__(16) float  Bs [TKV][130];  // [kk][code]

    const int tid = threadIdx.x;
    const int tx  = tid & 15;
    const int ty  = tid >> 4;
    const int rowBase = blockIdx.y * 128;
    const int cb      = blockIdx.x * 128;

    unsigned long long acc[8][4];
#pragma unroll
    for (int i = 0; i < 8; i++)
#pragma unroll
        for (int j = 0; j < 4; j++) acc[i][j] = 0ull;

    const float4* Af = reinterpret_cast<const float4*>(g_fmap);
    const float4* Bf = reinterpret_cast<const float4*>(cbk);

    for (int k0 = 0; k0 < DMODEL; k0 += TKV) {
        __syncthreads();
#pragma unroll
        for (int q = 0; q < 2; q++) {
            int li = tid + (q << 8);      // 0..511
            int r  = li >> 2;
            int kg = li & 3;
            float4 v = Af[(long long)(rowBase + r) * 64 + (k0 >> 2) + kg];
            As2[kg * 4 + 0][r] = make_float2(v.x, v.x);
            As2[kg * 4 + 1][r] = make_float2(v.y, v.y);
            As2[kg * 4 + 2][r] = make_float2(v.z, v.z);
            As2[kg * 4 + 3][r] = make_float2(v.w, v.w);
            float4 u = Bf[(long long)(cb + r) * 64 + (k0 >> 2) + kg];
            Bs[kg * 4 + 0][r] = u.x;
            Bs[kg * 4 + 1][r] = u.y;
            Bs[kg * 4 + 2][r] = u.z;
            Bs[kg * 4 + 3][r] = u.w;
        }
        __syncthreads();

#pragma unroll
        for (int kk = 0; kk < TKV; kk++) {
            unsigned long long a[8], bq[4];
#pragma unroll
            for (int i = 0; i < 8; i++)
                a[i] = *reinterpret_cast<const unsigned long long*>(&As2[kk][ty * 8 + i]);
#pragma unroll
            for (int j = 0; j < 4; j++)
                bq[j] = *reinterpret_cast<const unsigned long long*>(&Bs[kk][2 * tx + 32 * j]);
#pragma unroll
            for (int i = 0; i < 8; i++)
#pragma unroll
                for (int j = 0; j < 4; j++) fma2(acc[i][j], a[i], bq[j]);
        }
    }

    // distances, per-thread argmin, 16-lane reduce, global atomic combine
#pragma unroll
    for (int i = 0; i < 8; i++) {
        float bv = __int_as_float(0x7f800000);  // +inf
        int   bc = 0;
#pragma unroll
        for (int j = 0; j < 4; j++) {
            float lo, hi;
            unpack2(acc[i][j], lo, hi);
            int c0 = cb + 2 * tx + 32 * j;
            float d0 = fmaf(-2.f, lo, g_c2[c0]);
            float d1 = fmaf(-2.f, hi, g_c2[c0 + 1]);
            if (d0 < bv) { bv = d0; bc = c0; }
            if (d1 < bv) { bv = d1; bc = c0 + 1; }
        }
        unsigned long long key = ((unsigned long long)fenc(bv) << 32) | (unsigned)bc;
#pragma unroll
        for (int off = 8; off >= 1; off >>= 1) {
            unsigned long long o = __shfl_xor_sync(0xffffffffu, key, off);
            if (o < key) key = o;
        }
        if (tx == 0)
            atomicMin(&g_best[rowBase + ty * 8 + i], key);
    }
}

// =====================================================================
// Kernel 4: gather codebook rows -> NCHW quant output, indices, vq loss part
// grid: 2048 = (b, h); block 256
// =====================================================================
__global__ __launch_bounds__(256) void gather_kernel(const float* __restrict__ cbk,
                                                     float* __restrict__ out)
{
    __shared__ int   s_idx[128];
    __shared__ float s_val[128];

    const int bx  = blockIdx.x;
    const int tid = threadIdx.x;
    const int b   = bx >> 7;
    const int h   = bx & 127;

    if (tid < 128) {
        unsigned long long key = g_best[bx * 128 + tid];
        s_idx[tid] = (int)(unsigned)(key & 0xffffffffull);
        s_val[tid] = fdec((unsigned)(key >> 32));   // c^2 - 2 x.c of winner
    }
    __syncthreads();

    // reduce s_val for loss partial
    for (int s = 64; s > 0; s >>= 1) {
        if (tid < s) s_val[tid] += s_val[tid + s];
        __syncthreads();
    }
    if (tid == 0) g_vq_partial[bx] = s_val[0];

    // quant: NCHW writes, coalesced over w
    const int w    = tid & 127;
    const int doff = tid >> 7;
    const int myIdx = s_idx[w];
    for (int db = 0; db < DMODEL; db += 2) {
        int d = db + doff;
        float qv = cbk[myIdx * DMODEL + d];
        out[(((long long)(b * DMODEL + d) * 128 + h) << 7) + w] = qv;
    }

    // indices (cast to float)
    if (tid < 128)
        out[QUANT_ELEMS + (long long)bx * 128 + tid] = (float)s_idx[tid];
}

// =====================================================================
// Kernel 5: final loss = (sum x^2 + sum (c^2-2x.c)) / (B*N*D)
// =====================================================================
__global__ void loss_kernel(float* __restrict__ out)
{
    __shared__ float red[256];
    float s = 0.f;
    for (int i = threadIdx.x; i < 2048; i += 256)
        s += g_conv_partial[i] + g_vq_partial[i];
    red[threadIdx.x] = s;
    __syncthreads();
    for (int st = 128; st > 0; st >>= 1) {
        if (threadIdx.x < st) red[threadIdx.x] += red[threadIdx.x + st];
        __syncthreads();
    }
    if (threadIdx.x == 0)
        out[QUANT_ELEMS + IDX_ELEMS] = red[0] * (1.0f / 67108864.0f);
}

// =====================================================================
extern "C" void kernel_launch(void* const* d_in, const int* in_sizes, int n_in,
                              void* d_out, int out_size)
{
    (void)in_sizes; (void)n_in; (void)out_size;
    const float* x    = (const float*)d_in[0];
    const float* cw   = (const float*)d_in[1];
    const float* cbia = (const float*)d_in[2];
    const float* gam  = (const float*)d_in[3];
    const float* bet  = (const float*)d_in[4];
    const float* mu   = (const float*)d_in[5];
    const float* var  = (const float*)d_in[6];
    const float* cbk  = (const float*)d_in[7];
    float* out = (float*)d_out;

    void* bestPtr = nullptr;
    cudaGetSymbolAddress(&bestPtr, g_best);
    cudaMemsetAsync(bestPtr, 0xFF, (size_t)NROWS * sizeof(unsigned long long));

    conv_kernel<<<2048, 256>>>(x, cw, cbia, gam, bet, mu, var);
    c2_kernel<<<8, 256>>>(cbk);
    vq_kernel<<<dim3(4, 2048), 256>>>(cbk);
    gather_kernel<<<2048, 256>>>(cbk, out);
    loss_kernel<<<1, 256>>>(out);
}